// round 15
// baseline (speedup 1.0000x reference)
#include <cuda_runtime.h>
#include <cuda_bf16.h>
#include <math.h>
#include <stdint.h>

#define NN 8192
#define DD 64
#define ONES 0x3F803F80u

// ---------------- device scratch (allocation-free) ----------------
__device__ float g_rowsum[NN];
__device__ float g_colsum[NN];
__device__ __align__(16) __nv_bfloat16 g_adjbf[67108864];  // adj bf16 row-major
__device__ __align__(16) __nv_bfloat16 g_Qt[128 * NN];     // Q^T [n][k]
__device__ __align__(16) __nv_bfloat16 g_Pt[128 * NN];     // P^T [n][k]
__device__ __align__(16) float g_RiP[2][NN * 128];         // adj   @ Q split-K partials
__device__ __align__(16) float g_RuP[2][NN * 128];         // adj^T @ P split-K partials

__device__ __forceinline__ uint32_t smem_u32(const void* p) {
    uint32_t a;
    asm("{ .reg .u64 t; cvta.to.shared.u64 t, %1; cvt.u32.u64 %0, t; }" : "=r"(a) : "l"(p));
    return a;
}
__device__ __forceinline__ void cpa16(uint32_t s, const void* g) {
    asm volatile("cp.async.cg.shared.global [%0], [%1], 16;" :: "r"(s), "l"(g) : "memory");
}
__device__ __forceinline__ void sts128(uint32_t s, uint4 v) {
    asm volatile("st.shared.v4.b32 [%0], {%1,%2,%3,%4};"
                 :: "r"(s), "r"(v.x), "r"(v.y), "r"(v.z), "r"(v.w) : "memory");
}
__device__ __forceinline__ uint32_t bf2pk(float lo, float hi) {
    __nv_bfloat162 b = __float22bfloat162_rn(make_float2(lo, hi));
    return *(uint32_t*)&b;
}
__device__ __forceinline__ void mma_bf16(float* c, uint32_t a0, uint32_t a1, uint32_t a2,
                                         uint32_t a3, uint32_t b0, uint32_t b1) {
    asm volatile(
        "mma.sync.aligned.m16n8k16.row.col.f32.bf16.bf16.f32 "
        "{%0,%1,%2,%3}, {%4,%5,%6,%7}, {%8,%9}, {%0,%1,%2,%3};"
        : "+f"(c[0]), "+f"(c[1]), "+f"(c[2]), "+f"(c[3])
        : "r"(a0), "r"(a1), "r"(a2), "r"(a3), "r"(b0), "r"(b1));
}

// ---------------- 1) zero colsum (consumed by convsum atomics) ----------------
__global__ void zero_kernel() {
    int i = blockIdx.x * 256 + threadIdx.x;
    if (i < NN) g_colsum[i] = 0.f;
}

// ---------------- 2) FUSED convert fp32->bf16 + tensor-core row/col sums ----------------
// grid 128: CTA owns 64-row slab; 64 tiles of [64 rows x 128 cols].
// Double-buffered smem, ONE sync per tile: convert+store buf[it&1] -> prefetch it+1 ->
// sync -> mma sums on buf[it&1]. Rowsum: warps 0-3 (exclusive rows, direct store).
// Colsum: all warps via ldmatrix.trans + atomics (array pre-zeroed by zero_kernel).
__global__ void __launch_bounds__(256) convsum_kernel(const float* __restrict__ adj) {
    __shared__ __align__(16) __nv_bfloat16 st[2][64 * 128];
    int tid = threadIdx.x, lane = tid & 31, wid = tid >> 5;
    int r0 = blockIdx.x * 64;

    int lr = tid >> 2;           // row within tile
    int c0 = (tid & 3) * 32;     // col base (32 contiguous elements)
    const float* gp = adj + (size_t)(r0 + lr) * NN + c0;
    __nv_bfloat16* op = g_adjbf + (size_t)(r0 + lr) * NN + c0;
    uint32_t sbase = smem_u32(st);
    uint32_t sto[4];
#pragma unroll
    for (int j = 0; j < 4; j++)
        sto[j] = sbase + lr * 256 + ((((tid & 3) * 4 + j) ^ (lr & 7)) << 4);

    float4 ra[8];
#pragma unroll
    for (int j = 0; j < 8; j++) ra[j] = *(const float4*)(gp + j * 4);

    float rc[4] = {0.f, 0.f, 0.f, 0.f};  // rowsum accum (warps 0-3)

    // rowsum ldmatrix constants (warps 0-3)
    int aRow = (wid & 3) * 16 + (lane & 15);
    int ax = aRow & 7;
    int ahl = lane >> 4;
    // colsum ldmatrix constants
    int srow0 = ((lane >> 4) & 1) * 8 + (lane & 7);
    int scc = wid * 2 + ((lane >> 3) & 1);

    for (int it = 0; it < 64; it++) {
        uint32_t boff = (it & 1) * 16384;
        // convert + store (gmem + smem buf[it&1])
#pragma unroll
        for (int j = 0; j < 4; j++) {
            uint4 pk;
            pk.x = bf2pk(ra[2 * j].x, ra[2 * j].y);
            pk.y = bf2pk(ra[2 * j].z, ra[2 * j].w);
            pk.z = bf2pk(ra[2 * j + 1].x, ra[2 * j + 1].y);
            pk.w = bf2pk(ra[2 * j + 1].z, ra[2 * j + 1].w);
            *(uint4*)(op + (size_t)it * 128 + j * 8) = pk;
            sts128(sto[j] + boff, pk);
        }
        // prefetch next tile (overlaps with mma below)
        if (it + 1 < 64) {
            const float* np = gp + (size_t)(it + 1) * 128;
#pragma unroll
            for (int j = 0; j < 8; j++) ra[j] = *(const float4*)(np + j * 4);
        }
        __syncthreads();
        uint32_t buf = sbase + boff;

        // rowsum: warps 0-3
        if (wid < 4) {
#pragma unroll
            for (int kc = 0; kc < 8; kc++) {
                uint32_t a0, a1, a2, a3;
                uint32_t addr = buf + aRow * 256 + ((((kc << 1) | ahl) ^ ax) << 4);
                asm volatile("ldmatrix.sync.aligned.m8n8.x4.shared.b16 {%0,%1,%2,%3}, [%4];"
                             : "=r"(a0), "=r"(a1), "=r"(a2), "=r"(a3) : "r"(addr));
                mma_bf16(rc, a0, a1, a2, a3, ONES, ONES);
            }
        }
        // colsum: all warps, 16 cols each
        float cc0[4] = {0.f, 0.f, 0.f, 0.f}, cc1[4] = {0.f, 0.f, 0.f, 0.f};
#pragma unroll
        for (int kc = 0; kc < 4; kc++) {
            int srow = kc * 16 + srow0;
            uint32_t b0, b1, b2, b3;
            uint32_t addr = buf + srow * 256 + ((scc ^ (srow & 7)) << 4);
            asm volatile("ldmatrix.sync.aligned.m8n8.x4.trans.shared.b16 {%0,%1,%2,%3}, [%4];"
                         : "=r"(b0), "=r"(b1), "=r"(b2), "=r"(b3) : "r"(addr));
            mma_bf16(cc0, ONES, ONES, ONES, ONES, b0, b2);
            mma_bf16(cc1, ONES, ONES, ONES, ONES, b1, b3);
        }
        if (lane < 4) {
            int colb = it * 128 + wid * 16 + 2 * lane;
            atomicAdd(&g_colsum[colb + 0], cc0[0]);
            atomicAdd(&g_colsum[colb + 1], cc0[1]);
            atomicAdd(&g_colsum[colb + 8], cc1[0]);
            atomicAdd(&g_colsum[colb + 9], cc1[1]);
        }
    }

    if (wid < 4 && (lane & 3) == 0) {
        int row = r0 + (wid & 3) * 16 + (lane >> 2);
        g_rowsum[row] = rc[0];
        g_rowsum[row + 8] = rc[2];
    }
}

// ---------------- 3) build Qt/Pt (bf16, [n][k]); 16 k-rows per block ----------------
__global__ void __launch_bounds__(256) prep_kernel(const float* __restrict__ user,
                                                   const float* __restrict__ item,
                                                   const float* __restrict__ W1) {
    int var = blockIdx.y;  // 0 -> Pt (src=item, scale=rsqrt(rowsum)), 1 -> Qt
    const float* src = var ? user : item;
    const float* pas = var ? item : user;
    const float* sums = var ? g_colsum : g_rowsum;
    __nv_bfloat16* out = var ? g_Qt : g_Pt;

    __shared__ __align__(16) float Ws[DD * DD];
    __shared__ float Xs[16 * DD];
    __shared__ __nv_bfloat16 T[128 * 18];
    int tid = threadIdx.x;
    for (int i = tid; i < DD * DD; i += 256) Ws[i] = W1[i];
    int k0 = blockIdx.x * 16;
    for (int i = tid; i < 16 * DD; i += 256) Xs[i] = src[k0 * DD + i];
    __syncthreads();

    int row = tid >> 4;
    int g4 = (tid & 15) * 4;
    float a0 = 0.f, a1 = 0.f, a2 = 0.f, a3 = 0.f;
#pragma unroll 8
    for (int k = 0; k < DD; k++) {
        float x = Xs[row * DD + k];
        float4 w = *(const float4*)&Ws[k * DD + g4];
        a0 += x * w.x; a1 += x * w.y; a2 += x * w.z; a3 += x * w.w;
    }
    int gr = k0 + row;
    float s = rsqrtf(sums[gr]);
    T[(g4 + 0) * 18 + row] = __float2bfloat16(s * a0);
    T[(g4 + 1) * 18 + row] = __float2bfloat16(s * a1);
    T[(g4 + 2) * 18 + row] = __float2bfloat16(s * a2);
    T[(g4 + 3) * 18 + row] = __float2bfloat16(s * a3);
    const float* p = pas + gr * DD;
#pragma unroll
    for (int j = 0; j < 4; j++)
        T[(64 + g4 + j) * 18 + row] = __float2bfloat16(s * p[g4 + j]);
    __syncthreads();

    if (tid < 128) {
        int n = tid;
        __align__(16) __nv_bfloat16 v[16];
#pragma unroll
        for (int k = 0; k < 16; k++) v[k] = T[n * 18 + k];
        uint4* dst = (uint4*)(out + (size_t)n * NN + k0);
        dst[0] = ((uint4*)v)[0];
        dst[1] = ((uint4*)v)[1];
    }
}

// ---------------- 4) GEMMs: split-K=2, ping-pong pipeline, occupancy 2 (R14 proven) ----
#define NST 2
#define ASTG 16384
#define NITER2 64
#define SMEM_GEMM 67584   // >= max(2*NST*ASTG=64KB, transpose 128*132*4=67584)

__global__ void __launch_bounds__(256, 2) gemm_kernel() {
    extern __shared__ char sm[];
    uint32_t sA = smem_u32(sm);
    uint32_t sB = sA + NST * ASTG;

    int tid = threadIdx.x;
    int lane = tid & 31, wid = tid >> 5;
    int warpM = wid & 3, warpN = wid >> 2;  // 4x2 warps, warp tile 32m x 64n
    int z = blockIdx.z;
    size_t kbase = (size_t)z * 4096;

    float c[2][8][4];
#pragma unroll
    for (int f = 0; f < 2; f++)
#pragma unroll
        for (int n = 0; n < 8; n++)
#pragma unroll
            for (int j = 0; j < 4; j++) c[f][n][j] = 0.f;

    if (blockIdx.y == 0) {
        // ---------------- GEMM1: RiP[z] = adjbf @ Qt (K-half) ----------------
        int m0 = blockIdx.x * 128;
        float* Cg = g_RiP[z];
        int lr = tid >> 1, lc0 = (tid & 1) * 4;
        const char* gAp = (const char*)(g_adjbf + (size_t)(m0 + lr) * NN + kbase) + lc0 * 16;
        const char* gBp = (const char*)(g_Qt + (size_t)lr * NN + kbase) + lc0 * 16;
        uint32_t sto[4];
#pragma unroll
        for (int j = 0; j < 4; j++)
            sto[j] = lr * 128 + (((lc0 + j) ^ (lr & 7)) << 4);

        int aRow[2], aX[2];
#pragma unroll
        for (int f = 0; f < 2; f++) {
            aRow[f] = warpM * 32 + f * 16 + (lane & 15);
            aX[f] = aRow[f] & 7;
        }
        int ah = lane >> 4;
        int bRow[4], bX[4];
#pragma unroll
        for (int g = 0; g < 4; g++) {
            bRow[g] = warpN * 64 + g * 16 + (lane >> 4) * 8 + (lane & 7);
            bX[g] = bRow[g] & 7;
        }
        int bh = (lane >> 3) & 1;

#pragma unroll
        for (int j = 0; j < 4; j++) {
            cpa16(sA + sto[j], gAp + j * 16);
            cpa16(sB + sto[j], gBp + j * 16);
        }
        asm volatile("cp.async.commit_group;" ::: "memory");

        for (int it = 0; it < NITER2; it++) {
            asm volatile("cp.async.wait_group 0;" ::: "memory");
            __syncthreads();
            if (it + 1 < NITER2) {
                int s = (it + 1) & 1;
                size_t kb = (size_t)(it + 1) * 128;
#pragma unroll
                for (int j = 0; j < 4; j++) {
                    cpa16(sA + s * ASTG + sto[j], gAp + kb + j * 16);
                    cpa16(sB + s * ASTG + sto[j], gBp + kb + j * 16);
                }
                asm volatile("cp.async.commit_group;" ::: "memory");
            }
            uint32_t ba = sA + (it & 1) * ASTG;
            uint32_t bb = sB + (it & 1) * ASTG;
#pragma unroll
            for (int ks = 0; ks < 4; ks++) {
                uint32_t am[2][4], bn[4][4];
#pragma unroll
                for (int f = 0; f < 2; f++) {
                    uint32_t addr = ba + aRow[f] * 128 + ((((ks << 1) | ah) ^ aX[f]) << 4);
                    asm volatile("ldmatrix.sync.aligned.m8n8.x4.shared.b16 {%0,%1,%2,%3}, [%4];"
                                 : "=r"(am[f][0]), "=r"(am[f][1]), "=r"(am[f][2]), "=r"(am[f][3])
                                 : "r"(addr));
                }
#pragma unroll
                for (int g = 0; g < 4; g++) {
                    uint32_t addr = bb + bRow[g] * 128 + ((((ks << 1) | bh) ^ bX[g]) << 4);
                    asm volatile("ldmatrix.sync.aligned.m8n8.x4.shared.b16 {%0,%1,%2,%3}, [%4];"
                                 : "=r"(bn[g][0]), "=r"(bn[g][1]), "=r"(bn[g][2]), "=r"(bn[g][3])
                                 : "r"(addr));
                }
#pragma unroll
                for (int f = 0; f < 2; f++)
#pragma unroll
                    for (int g = 0; g < 4; g++) {
                        mma_bf16(c[f][g * 2], am[f][0], am[f][1], am[f][2], am[f][3],
                                 bn[g][0], bn[g][1]);
                        mma_bf16(c[f][g * 2 + 1], am[f][0], am[f][1], am[f][2], am[f][3],
                                 bn[g][2], bn[g][3]);
                    }
            }
        }
#pragma unroll
        for (int f = 0; f < 2; f++) {
            int row = m0 + warpM * 32 + f * 16 + (lane >> 2);
#pragma unroll
            for (int n = 0; n < 8; n++) {
                int col = warpN * 64 + n * 8 + (lane & 3) * 2;
                *(float2*)&Cg[(size_t)row * 128 + col] = make_float2(c[f][n][0], c[f][n][1]);
                *(float2*)&Cg[(size_t)(row + 8) * 128 + col] = make_float2(c[f][n][2], c[f][n][3]);
            }
        }
    } else {
        // ---------------- GEMM2: RuT partial = Pt @ adjbf[Khalf, n-tile] ----------------
        int n0 = blockIdx.x * 128;
        float* Cg = g_RuP[z];
        int lrA = tid >> 1, lcA = (tid & 1) * 4;
        const char* gAp = (const char*)(g_Pt + (size_t)lrA * NN + kbase) + lcA * 16;
        uint32_t stoA[4];
#pragma unroll
        for (int j = 0; j < 4; j++)
            stoA[j] = lrA * 128 + (((lcA + j) ^ (lrA & 7)) << 4);

        int lrB = tid >> 2, lcB = (tid & 3) * 4;
        const char* gBp = (const char*)(g_adjbf + (size_t)(kbase + lrB) * NN + n0) + lcB * 16;
        uint32_t stoB[4];
#pragma unroll
        for (int j = 0; j < 4; j++)
            stoB[j] = lrB * 256 + (((lcB + j) ^ (lrB & 7)) << 4);

        int aRow[2], aX[2];
#pragma unroll
        for (int f = 0; f < 2; f++) {
            aRow[f] = warpM * 32 + f * 16 + (lane & 15);
            aX[f] = aRow[f] & 7;
        }
        int ah = lane >> 4;
        int srow0 = ((lane >> 4) & 1) * 8 + (lane & 7);
        int scb = (lane >> 3) & 1;

#pragma unroll
        for (int j = 0; j < 4; j++) {
            cpa16(sA + stoA[j], gAp + j * 16);
            cpa16(sB + stoB[j], gBp + j * 16);
        }
        asm volatile("cp.async.commit_group;" ::: "memory");

        for (int it = 0; it < NITER2; it++) {
            asm volatile("cp.async.wait_group 0;" ::: "memory");
            __syncthreads();
            if (it + 1 < NITER2) {
                int s = (it + 1) & 1;
                size_t kit = (size_t)(it + 1);
#pragma unroll
                for (int j = 0; j < 4; j++) {
                    cpa16(sA + s * ASTG + stoA[j], gAp + kit * 128 + j * 16);
                    cpa16(sB + s * ASTG + stoB[j], gBp + kit * 64 * NN * 2 + j * 16);
                }
                asm volatile("cp.async.commit_group;" ::: "memory");
            }
            uint32_t ba = sA + (it & 1) * ASTG;
            uint32_t bb = sB + (it & 1) * ASTG;
#pragma unroll
            for (int ks = 0; ks < 4; ks++) {
                uint32_t am[2][4], bn[4][4];
#pragma unroll
                for (int f = 0; f < 2; f++) {
                    uint32_t addr = ba + aRow[f] * 128 + ((((ks << 1) | ah) ^ aX[f]) << 4);
                    asm volatile("ldmatrix.sync.aligned.m8n8.x4.shared.b16 {%0,%1,%2,%3}, [%4];"
                                 : "=r"(am[f][0]), "=r"(am[f][1]), "=r"(am[f][2]), "=r"(am[f][3])
                                 : "r"(addr));
                }
                int srow = ks * 16 + srow0;
                int sxr = srow & 7;
#pragma unroll
                for (int g = 0; g < 4; g++) {
                    int sc = warpN * 8 + g * 2 + scb;
                    uint32_t addr = bb + srow * 256 + ((sc ^ sxr) << 4);
                    asm volatile("ldmatrix.sync.aligned.m8n8.x4.trans.shared.b16 {%0,%1,%2,%3}, [%4];"
                                 : "=r"(bn[g][0]), "=r"(bn[g][1]), "=r"(bn[g][2]), "=r"(bn[g][3])
                                 : "r"(addr));
                }
#pragma unroll
                for (int f = 0; f < 2; f++)
#pragma unroll
                    for (int g = 0; g < 4; g++) {
                        mma_bf16(c[f][g * 2], am[f][0], am[f][1], am[f][2], am[f][3],
                                 bn[g][0], bn[g][2]);
                        mma_bf16(c[f][g * 2 + 1], am[f][0], am[f][1], am[f][2], am[f][3],
                                 bn[g][1], bn[g][3]);
                    }
            }
        }

        // transpose epilogue
        __syncthreads();
        float* tr = (float*)sm;
#pragma unroll
        for (int f = 0; f < 2; f++) {
            int m = warpM * 32 + f * 16 + (lane >> 2);
#pragma unroll
            for (int n = 0; n < 8; n++) {
                int nc = warpN * 64 + n * 8 + (lane & 3) * 2;
                tr[nc * 132 + m] = c[f][n][0];
                tr[(nc + 1) * 132 + m] = c[f][n][1];
                tr[nc * 132 + m + 8] = c[f][n][2];
                tr[(nc + 1) * 132 + m + 8] = c[f][n][3];
            }
        }
        __syncthreads();
        for (int i = tid; i < 128 * 32; i += 256) {
            int r = i >> 5, q = i & 31;
            float4 v = *(float4*)&tr[r * 132 + q * 4];
            *(float4*)&Cg[(size_t)(n0 + r) * 128 + q * 4] = v;
        }
    }
}

// ---------------- 5) epilogue (sums split-K partials, inline rsqrt) ----------------
__global__ void __launch_bounds__(256) final_kernel(const float* __restrict__ user,
                                                    const float* __restrict__ item,
                                                    const float* __restrict__ W2,
                                                    float* __restrict__ out) {
    int var = blockIdx.y;
    const float* R0 = var ? g_RiP[0] : g_RuP[0];
    const float* R1 = var ? g_RiP[1] : g_RuP[1];
    const float* sums = var ? g_rowsum : g_colsum;
    const float* src = var ? user : item;
    const float* tgt = var ? item : user;
    float* o = out + (size_t)var * NN * DD;

    __shared__ __align__(16) float Ws[DD * DD];
    __shared__ float Hs[16 * DD];
    int tid = threadIdx.x;
    for (int i = tid; i < DD * DD; i += 256) Ws[i] = W2[i];

    int r0 = blockIdx.x * 16;
    int row = tid >> 4;
    int cg = (tid & 15) * 4;
    int gr = r0 + row;
    float s = rsqrtf(sums[gr]);
#pragma unroll
    for (int j = 0; j < 4; j++) {
        float rv = R0[gr * 128 + 64 + cg + j] + R1[gr * 128 + 64 + cg + j];
        Hs[row * DD + cg + j] = src[gr * DD + cg + j] * (s * rv);
    }
    __syncthreads();

    float acc[4] = {0.f, 0.f, 0.f, 0.f};
#pragma unroll 8
    for (int k = 0; k < DD; k++) {
        float hh = Hs[row * DD + k];
        float4 w = *(const float4*)&Ws[k * DD + cg];
        acc[0] += hh * w.x; acc[1] += hh * w.y; acc[2] += hh * w.z; acc[3] += hh * w.w;
    }
#pragma unroll
    for (int j = 0; j < 4; j++) {
        float rv = R0[gr * 128 + cg + j] + R1[gr * 128 + cg + j];
        float x = s * rv + acc[j] + tgt[gr * DD + cg + j];
        o[gr * DD + cg + j] = x > 0.f ? x : 0.2f * x;
    }
}

// ---------------- launch ----------------
extern "C" void kernel_launch(void* const* d_in, const int* in_sizes, int n_in,
                              void* d_out, int out_size) {
    const float* user = (const float*)d_in[0];
    const float* item = (const float*)d_in[1];
    const float* adj  = (const float*)d_in[2];
    const float* W1   = (const float*)d_in[3];
    const float* W2   = (const float*)d_in[4];
    float* out = (float*)d_out;

    cudaFuncSetAttribute(gemm_kernel, cudaFuncAttributeMaxDynamicSharedMemorySize, SMEM_GEMM);

    zero_kernel<<<32, 256>>>();
    convsum_kernel<<<128, 256>>>(adj);
    prep_kernel<<<dim3(512, 2), 256>>>(user, item, W1);
    gemm_kernel<<<dim3(64, 2, 2), 256, SMEM_GEMM>>>();
    final_kernel<<<dim3(512, 2), 256>>>(user, item, W2, out);
}

// round 16
// speedup vs baseline: 1.0602x; 1.0602x over previous
#include <cuda_runtime.h>
#include <cuda_bf16.h>
#include <math.h>
#include <stdint.h>

#define NN 8192
#define DD 64
#define ONES 0x3F803F80u

// ---------------- device scratch (allocation-free) ----------------
__device__ float g_rowsum[NN];
__device__ float g_colsum[NN];
__device__ __align__(16) __nv_bfloat16 g_adjbf[67108864];  // adj bf16 row-major
__device__ __align__(16) __nv_bfloat16 g_Qt[128 * NN];     // Q^T [n][k]
__device__ __align__(16) __nv_bfloat16 g_Pt[128 * NN];     // P^T [n][k]
__device__ __align__(16) float g_RiP[2][NN * 128];         // adj   @ Q split-K partials
__device__ __align__(16) float g_RuP[2][NN * 128];         // adj^T @ P split-K partials

__device__ __forceinline__ uint32_t smem_u32(const void* p) {
    uint32_t a;
    asm("{ .reg .u64 t; cvta.to.shared.u64 t, %1; cvt.u32.u64 %0, t; }" : "=r"(a) : "l"(p));
    return a;
}
__device__ __forceinline__ void cpa16(uint32_t s, const void* g) {
    asm volatile("cp.async.cg.shared.global [%0], [%1], 16;" :: "r"(s), "l"(g) : "memory");
}
__device__ __forceinline__ uint32_t bf2pk(float lo, float hi) {
    __nv_bfloat162 b = __float22bfloat162_rn(make_float2(lo, hi));
    return *(uint32_t*)&b;
}
__device__ __forceinline__ void mma_bf16(float* c, uint32_t a0, uint32_t a1, uint32_t a2,
                                         uint32_t a3, uint32_t b0, uint32_t b1) {
    asm volatile(
        "mma.sync.aligned.m16n8k16.row.col.f32.bf16.bf16.f32 "
        "{%0,%1,%2,%3}, {%4,%5,%6,%7}, {%8,%9}, {%0,%1,%2,%3};"
        : "+f"(c[0]), "+f"(c[1]), "+f"(c[2]), "+f"(c[3])
        : "r"(a0), "r"(a1), "r"(a2), "r"(a3), "r"(b0), "r"(b1));
}

// ---------------- 1) streaming convert fp32 -> bf16 (+ zero colsum), 4-deep MLP ----------
// grid 4096 x 256. Each iteration issues 4 independent coalesced float4 loads
// (block-strided batches of 256) before any convert/store -> guaranteed MLP=4.
__global__ void __launch_bounds__(256) convert_kernel(const float* __restrict__ adj) {
    int tid = threadIdx.x;
    int gid = blockIdx.x * 256 + tid;
    if (gid < NN) g_colsum[gid] = 0.f;  // re-zeroed every replay; consumed by sums_kernel

    const int NF4 = NN * NN / 4;                 // 16M float4s
    const float4* in = (const float4*)adj;
    uint2* outp = (uint2*)g_adjbf;
    // batch base: block covers 1024 consecutive float4s per pass
    for (int base = blockIdx.x * 1024 + tid; base < NF4; base += 4096 * 1024) {
        float4 v0 = in[base];
        float4 v1 = in[base + 256];
        float4 v2 = in[base + 512];
        float4 v3 = in[base + 768];
        uint2 o0, o1, o2, o3;
        o0.x = bf2pk(v0.x, v0.y); o0.y = bf2pk(v0.z, v0.w);
        o1.x = bf2pk(v1.x, v1.y); o1.y = bf2pk(v1.z, v1.w);
        o2.x = bf2pk(v2.x, v2.y); o2.y = bf2pk(v2.z, v2.w);
        o3.x = bf2pk(v3.x, v3.y); o3.y = bf2pk(v3.z, v3.w);
        outp[base] = o0;
        outp[base + 256] = o1;
        outp[base + 512] = o2;
        outp[base + 768] = o3;
    }
}

// ---------------- 2) tensor-core row/col sums of adjbf (R14 proven) ----------------
#define SROWS 64
#define SCOLS 128
__global__ void __launch_bounds__(256) sums_kernel() {
    __shared__ __align__(16) __nv_bfloat16 st[3][SROWS * SCOLS];
    int tid = threadIdx.x, lane = tid & 31, wid = tid >> 5;
    int r0 = blockIdx.x * SROWS;

    int lr = tid >> 2, lc0 = (tid & 3) * 4;
    const char* gp = (const char*)(g_adjbf + (size_t)(r0 + lr) * NN) + lc0 * 16;
    uint32_t sbase = smem_u32(st);
    uint32_t sto[4];
#pragma unroll
    for (int j = 0; j < 4; j++)
        sto[j] = lr * 256 + (((lc0 + j) ^ (lr & 7)) << 4);

#pragma unroll
    for (int s = 0; s < 2; s++) {
#pragma unroll
        for (int j = 0; j < 4; j++)
            cpa16(sbase + s * (SROWS * SCOLS * 2) + sto[j], gp + (size_t)s * 256 + j * 16);
        asm volatile("cp.async.commit_group;" ::: "memory");
    }

    float rc[4] = {0.f, 0.f, 0.f, 0.f};

    for (int it = 0; it < 64; it++) {
        if (it < 62) asm volatile("cp.async.wait_group 1;" ::: "memory");
        else         asm volatile("cp.async.wait_group 0;" ::: "memory");
        __syncthreads();
        if (it + 2 < 64) {
            int s = (it + 2) % 3;
#pragma unroll
            for (int j = 0; j < 4; j++)
                cpa16(sbase + s * (SROWS * SCOLS * 2) + sto[j],
                      gp + (size_t)(it + 2) * 256 + j * 16);
            asm volatile("cp.async.commit_group;" ::: "memory");
        }
        uint32_t buf = sbase + (it % 3) * (SROWS * SCOLS * 2);

        if (wid < 4) {
            int aRow = wid * 16 + (lane & 15);
            int ax = aRow & 7;
#pragma unroll
            for (int kc = 0; kc < 8; kc++) {
                uint32_t a0, a1, a2, a3;
                uint32_t addr = buf + aRow * 256 + ((((kc << 1) | (lane >> 4)) ^ ax) << 4);
                asm volatile("ldmatrix.sync.aligned.m8n8.x4.shared.b16 {%0,%1,%2,%3}, [%4];"
                             : "=r"(a0), "=r"(a1), "=r"(a2), "=r"(a3) : "r"(addr));
                mma_bf16(rc, a0, a1, a2, a3, ONES, ONES);
            }
        }

        float cc0[4] = {0.f, 0.f, 0.f, 0.f}, cc1[4] = {0.f, 0.f, 0.f, 0.f};
        int srow0 = ((lane >> 4) & 1) * 8 + (lane & 7);
        int sc = wid * 2 + ((lane >> 3) & 1);
#pragma unroll
        for (int kc = 0; kc < 4; kc++) {
            int srow = kc * 16 + srow0;
            uint32_t b0, b1, b2, b3;
            uint32_t addr = buf + srow * 256 + ((sc ^ (srow & 7)) << 4);
            asm volatile("ldmatrix.sync.aligned.m8n8.x4.trans.shared.b16 {%0,%1,%2,%3}, [%4];"
                         : "=r"(b0), "=r"(b1), "=r"(b2), "=r"(b3) : "r"(addr));
            mma_bf16(cc0, ONES, ONES, ONES, ONES, b0, b2);
            mma_bf16(cc1, ONES, ONES, ONES, ONES, b1, b3);
        }
        if (lane < 4) {
            int colb = it * 128 + wid * 16 + 2 * lane;
            atomicAdd(&g_colsum[colb + 0], cc0[0]);
            atomicAdd(&g_colsum[colb + 1], cc0[1]);
            atomicAdd(&g_colsum[colb + 8], cc1[0]);
            atomicAdd(&g_colsum[colb + 9], cc1[1]);
        }
    }

    if (wid < 4 && (lane & 3) == 0) {
        int row = r0 + wid * 16 + (lane >> 2);
        g_rowsum[row] = rc[0];
        g_rowsum[row + 8] = rc[2];
    }
}

// ---------------- 3) build Qt/Pt (bf16, [n][k]); 16 k-rows per block ----------------
__global__ void __launch_bounds__(256) prep_kernel(const float* __restrict__ user,
                                                   const float* __restrict__ item,
                                                   const float* __restrict__ W1) {
    int var = blockIdx.y;  // 0 -> Pt (src=item, scale=rsqrt(rowsum)), 1 -> Qt
    const float* src = var ? user : item;
    const float* pas = var ? item : user;
    const float* sums = var ? g_colsum : g_rowsum;
    __nv_bfloat16* out = var ? g_Qt : g_Pt;

    __shared__ __align__(16) float Ws[DD * DD];
    __shared__ float Xs[16 * DD];
    __shared__ __nv_bfloat16 T[128 * 18];
    int tid = threadIdx.x;
    for (int i = tid; i < DD * DD; i += 256) Ws[i] = W1[i];
    int k0 = blockIdx.x * 16;
    for (int i = tid; i < 16 * DD; i += 256) Xs[i] = src[k0 * DD + i];
    __syncthreads();

    int row = tid >> 4;
    int g4 = (tid & 15) * 4;
    float a0 = 0.f, a1 = 0.f, a2 = 0.f, a3 = 0.f;
#pragma unroll 8
    for (int k = 0; k < DD; k++) {
        float x = Xs[row * DD + k];
        float4 w = *(const float4*)&Ws[k * DD + g4];
        a0 += x * w.x; a1 += x * w.y; a2 += x * w.z; a3 += x * w.w;
    }
    int gr = k0 + row;
    float s = rsqrtf(sums[gr]);
    T[(g4 + 0) * 18 + row] = __float2bfloat16(s * a0);
    T[(g4 + 1) * 18 + row] = __float2bfloat16(s * a1);
    T[(g4 + 2) * 18 + row] = __float2bfloat16(s * a2);
    T[(g4 + 3) * 18 + row] = __float2bfloat16(s * a3);
    const float* p = pas + gr * DD;
#pragma unroll
    for (int j = 0; j < 4; j++)
        T[(64 + g4 + j) * 18 + row] = __float2bfloat16(s * p[g4 + j]);
    __syncthreads();

    if (tid < 128) {
        int n = tid;
        __align__(16) __nv_bfloat16 v[16];
#pragma unroll
        for (int k = 0; k < 16; k++) v[k] = T[n * 18 + k];
        uint4* dst = (uint4*)(out + (size_t)n * NN + k0);
        dst[0] = ((uint4*)v)[0];
        dst[1] = ((uint4*)v)[1];
    }
}

// ---------------- 4) GEMMs: split-K=2, ping-pong pipeline, occupancy 2 (R14 proven) ----
#define NST 2
#define ASTG 16384
#define NITER2 64
#define SMEM_GEMM 67584   // >= max(2*NST*ASTG=64KB, transpose 128*132*4=67584)

__global__ void __launch_bounds__(256, 2) gemm_kernel() {
    extern __shared__ char sm[];
    uint32_t sA = smem_u32(sm);
    uint32_t sB = sA + NST * ASTG;

    int tid = threadIdx.x;
    int lane = tid & 31, wid = tid >> 5;
    int warpM = wid & 3, warpN = wid >> 2;  // 4x2 warps, warp tile 32m x 64n
    int z = blockIdx.z;
    size_t kbase = (size_t)z * 4096;

    float c[2][8][4];
#pragma unroll
    for (int f = 0; f < 2; f++)
#pragma unroll
        for (int n = 0; n < 8; n++)
#pragma unroll
            for (int j = 0; j < 4; j++) c[f][n][j] = 0.f;

    if (blockIdx.y == 0) {
        // ---------------- GEMM1: RiP[z] = adjbf @ Qt (K-half) ----------------
        int m0 = blockIdx.x * 128;
        float* Cg = g_RiP[z];
        int lr = tid >> 1, lc0 = (tid & 1) * 4;
        const char* gAp = (const char*)(g_adjbf + (size_t)(m0 + lr) * NN + kbase) + lc0 * 16;
        const char* gBp = (const char*)(g_Qt + (size_t)lr * NN + kbase) + lc0 * 16;
        uint32_t sto[4];
#pragma unroll
        for (int j = 0; j < 4; j++)
            sto[j] = lr * 128 + (((lc0 + j) ^ (lr & 7)) << 4);

        int aRow[2], aX[2];
#pragma unroll
        for (int f = 0; f < 2; f++) {
            aRow[f] = warpM * 32 + f * 16 + (lane & 15);
            aX[f] = aRow[f] & 7;
        }
        int ah = lane >> 4;
        int bRow[4], bX[4];
#pragma unroll
        for (int g = 0; g < 4; g++) {
            bRow[g] = warpN * 64 + g * 16 + (lane >> 4) * 8 + (lane & 7);
            bX[g] = bRow[g] & 7;
        }
        int bh = (lane >> 3) & 1;

#pragma unroll
        for (int j = 0; j < 4; j++) {
            cpa16(sA + sto[j], gAp + j * 16);
            cpa16(sB + sto[j], gBp + j * 16);
        }
        asm volatile("cp.async.commit_group;" ::: "memory");

        for (int it = 0; it < NITER2; it++) {
            asm volatile("cp.async.wait_group 0;" ::: "memory");
            __syncthreads();
            if (it + 1 < NITER2) {
                int s = (it + 1) & 1;
                size_t kb = (size_t)(it + 1) * 128;
#pragma unroll
                for (int j = 0; j < 4; j++) {
                    cpa16(sA + s * ASTG + sto[j], gAp + kb + j * 16);
                    cpa16(sB + s * ASTG + sto[j], gBp + kb + j * 16);
                }
                asm volatile("cp.async.commit_group;" ::: "memory");
            }
            uint32_t ba = sA + (it & 1) * ASTG;
            uint32_t bb = sB + (it & 1) * ASTG;
#pragma unroll
            for (int ks = 0; ks < 4; ks++) {
                uint32_t am[2][4], bn[4][4];
#pragma unroll
                for (int f = 0; f < 2; f++) {
                    uint32_t addr = ba + aRow[f] * 128 + ((((ks << 1) | ah) ^ aX[f]) << 4);
                    asm volatile("ldmatrix.sync.aligned.m8n8.x4.shared.b16 {%0,%1,%2,%3}, [%4];"
                                 : "=r"(am[f][0]), "=r"(am[f][1]), "=r"(am[f][2]), "=r"(am[f][3])
                                 : "r"(addr));
                }
#pragma unroll
                for (int g = 0; g < 4; g++) {
                    uint32_t addr = bb + bRow[g] * 128 + ((((ks << 1) | bh) ^ bX[g]) << 4);
                    asm volatile("ldmatrix.sync.aligned.m8n8.x4.shared.b16 {%0,%1,%2,%3}, [%4];"
                                 : "=r"(bn[g][0]), "=r"(bn[g][1]), "=r"(bn[g][2]), "=r"(bn[g][3])
                                 : "r"(addr));
                }
#pragma unroll
                for (int f = 0; f < 2; f++)
#pragma unroll
                    for (int g = 0; g < 4; g++) {
                        mma_bf16(c[f][g * 2], am[f][0], am[f][1], am[f][2], am[f][3],
                                 bn[g][0], bn[g][1]);
                        mma_bf16(c[f][g * 2 + 1], am[f][0], am[f][1], am[f][2], am[f][3],
                                 bn[g][2], bn[g][3]);
                    }
            }
        }
#pragma unroll
        for (int f = 0; f < 2; f++) {
            int row = m0 + warpM * 32 + f * 16 + (lane >> 2);
#pragma unroll
            for (int n = 0; n < 8; n++) {
                int col = warpN * 64 + n * 8 + (lane & 3) * 2;
                *(float2*)&Cg[(size_t)row * 128 + col] = make_float2(c[f][n][0], c[f][n][1]);
                *(float2*)&Cg[(size_t)(row + 8) * 128 + col] = make_float2(c[f][n][2], c[f][n][3]);
            }
        }
    } else {
        // ---------------- GEMM2: RuT partial = Pt @ adjbf[Khalf, n-tile] ----------------
        int n0 = blockIdx.x * 128;
        float* Cg = g_RuP[z];
        int lrA = tid >> 1, lcA = (tid & 1) * 4;
        const char* gAp = (const char*)(g_Pt + (size_t)lrA * NN + kbase) + lcA * 16;
        uint32_t stoA[4];
#pragma unroll
        for (int j = 0; j < 4; j++)
            stoA[j] = lrA * 128 + (((lcA + j) ^ (lrA & 7)) << 4);

        int lrB = tid >> 2, lcB = (tid & 3) * 4;
        const char* gBp = (const char*)(g_adjbf + (size_t)(kbase + lrB) * NN + n0) + lcB * 16;
        uint32_t stoB[4];
#pragma unroll
        for (int j = 0; j < 4; j++)
            stoB[j] = lrB * 256 + (((lcB + j) ^ (lrB & 7)) << 4);

        int aRow[2], aX[2];
#pragma unroll
        for (int f = 0; f < 2; f++) {
            aRow[f] = warpM * 32 + f * 16 + (lane & 15);
            aX[f] = aRow[f] & 7;
        }
        int ah = lane >> 4;
        int srow0 = ((lane >> 4) & 1) * 8 + (lane & 7);
        int scb = (lane >> 3) & 1;

#pragma unroll
        for (int j = 0; j < 4; j++) {
            cpa16(sA + stoA[j], gAp + j * 16);
            cpa16(sB + stoB[j], gBp + j * 16);
        }
        asm volatile("cp.async.commit_group;" ::: "memory");

        for (int it = 0; it < NITER2; it++) {
            asm volatile("cp.async.wait_group 0;" ::: "memory");
            __syncthreads();
            if (it + 1 < NITER2) {
                int s = (it + 1) & 1;
                size_t kit = (size_t)(it + 1);
#pragma unroll
                for (int j = 0; j < 4; j++) {
                    cpa16(sA + s * ASTG + stoA[j], gAp + kit * 128 + j * 16);
                    cpa16(sB + s * ASTG + stoB[j], gBp + kit * 64 * NN * 2 + j * 16);
                }
                asm volatile("cp.async.commit_group;" ::: "memory");
            }
            uint32_t ba = sA + (it & 1) * ASTG;
            uint32_t bb = sB + (it & 1) * ASTG;
#pragma unroll
            for (int ks = 0; ks < 4; ks++) {
                uint32_t am[2][4], bn[4][4];
#pragma unroll
                for (int f = 0; f < 2; f++) {
                    uint32_t addr = ba + aRow[f] * 128 + ((((ks << 1) | ah) ^ aX[f]) << 4);
                    asm volatile("ldmatrix.sync.aligned.m8n8.x4.shared.b16 {%0,%1,%2,%3}, [%4];"
                                 : "=r"(am[f][0]), "=r"(am[f][1]), "=r"(am[f][2]), "=r"(am[f][3])
                                 : "r"(addr));
                }
                int srow = ks * 16 + srow0;
                int sxr = srow & 7;
#pragma unroll
                for (int g = 0; g < 4; g++) {
                    int sc = warpN * 8 + g * 2 + scb;
                    uint32_t addr = bb + srow * 256 + ((sc ^ sxr) << 4);
                    asm volatile("ldmatrix.sync.aligned.m8n8.x4.trans.shared.b16 {%0,%1,%2,%3}, [%4];"
                                 : "=r"(bn[g][0]), "=r"(bn[g][1]), "=r"(bn[g][2]), "=r"(bn[g][3])
                                 : "r"(addr));
                }
#pragma unroll
                for (int f = 0; f < 2; f++)
#pragma unroll
                    for (int g = 0; g < 4; g++) {
                        mma_bf16(c[f][g * 2], am[f][0], am[f][1], am[f][2], am[f][3],
                                 bn[g][0], bn[g][2]);
                        mma_bf16(c[f][g * 2 + 1], am[f][0], am[f][1], am[f][2], am[f][3],
                                 bn[g][1], bn[g][3]);
                    }
            }
        }

        // transpose epilogue
        __syncthreads();
        float* tr = (float*)sm;
#pragma unroll
        for (int f = 0; f < 2; f++) {
            int m = warpM * 32 + f * 16 + (lane >> 2);
#pragma unroll
            for (int n = 0; n < 8; n++) {
                int nc = warpN * 64 + n * 8 + (lane & 3) * 2;
                tr[nc * 132 + m] = c[f][n][0];
                tr[(nc + 1) * 132 + m] = c[f][n][1];
                tr[nc * 132 + m + 8] = c[f][n][2];
                tr[(nc + 1) * 132 + m + 8] = c[f][n][3];
            }
        }
        __syncthreads();
        for (int i = tid; i < 128 * 32; i += 256) {
            int r = i >> 5, q = i & 31;
            float4 v = *(float4*)&tr[r * 132 + q * 4];
            *(float4*)&Cg[(size_t)(n0 + r) * 128 + q * 4] = v;
        }
    }
}

// ---------------- 5) epilogue (sums split-K partials, inline rsqrt) ----------------
__global__ void __launch_bounds__(256) final_kernel(const float* __restrict__ user,
                                                    const float* __restrict__ item,
                                                    const float* __restrict__ W2,
                                                    float* __restrict__ out) {
    int var = blockIdx.y;
    const float* R0 = var ? g_RiP[0] : g_RuP[0];
    const float* R1 = var ? g_RiP[1] : g_RuP[1];
    const float* sums = var ? g_rowsum : g_colsum;
    const float* src = var ? user : item;
    const float* tgt = var ? item : user;
    float* o = out + (size_t)var * NN * DD;

    __shared__ __align__(16) float Ws[DD * DD];
    __shared__ float Hs[16 * DD];
    int tid = threadIdx.x;
    for (int i = tid; i < DD * DD; i += 256) Ws[i] = W2[i];

    int r0 = blockIdx.x * 16;
    int row = tid >> 4;
    int cg = (tid & 15) * 4;
    int gr = r0 + row;
    float s = rsqrtf(sums[gr]);
#pragma unroll
    for (int j = 0; j < 4; j++) {
        float rv = R0[gr * 128 + 64 + cg + j] + R1[gr * 128 + 64 + cg + j];
        Hs[row * DD + cg + j] = src[gr * DD + cg + j] * (s * rv);
    }
    __syncthreads();

    float acc[4] = {0.f, 0.f, 0.f, 0.f};
#pragma unroll 8
    for (int k = 0; k < DD; k++) {
        float hh = Hs[row * DD + k];
        float4 w = *(const float4*)&Ws[k * DD + cg];
        acc[0] += hh * w.x; acc[1] += hh * w.y; acc[2] += hh * w.z; acc[3] += hh * w.w;
    }
#pragma unroll
    for (int j = 0; j < 4; j++) {
        float rv = R0[gr * 128 + cg + j] + R1[gr * 128 + cg + j];
        float x = s * rv + acc[j] + tgt[gr * DD + cg + j];
        o[gr * DD + cg + j] = x > 0.f ? x : 0.2f * x;
    }
}

// ---------------- launch ----------------
extern "C" void kernel_launch(void* const* d_in, const int* in_sizes, int n_in,
                              void* d_out, int out_size) {
    const float* user = (const float*)d_in[0];
    const float* item = (const float*)d_in[1];
    const float* adj  = (const float*)d_in[2];
    const float* W1   = (const float*)d_in[3];
    const float* W2   = (const float*)d_in[4];
    float* out = (float*)d_out;

    cudaFuncSetAttribute(gemm_kernel, cudaFuncAttributeMaxDynamicSharedMemorySize, SMEM_GEMM);

    convert_kernel<<<4096, 256>>>(adj);
    sums_kernel<<<128, 256>>>();
    prep_kernel<<<dim3(512, 2), 256>>>(user, item, W1);
    gemm_kernel<<<dim3(64, 2, 2), 256, SMEM_GEMM>>>();
    final_kernel<<<dim3(512, 2), 256>>>(user, item, W2, out);
}

// round 17
// speedup vs baseline: 1.0981x; 1.0358x over previous
#include <cuda_runtime.h>
#include <cuda_bf16.h>
#include <math.h>
#include <stdint.h>

#define NN 8192
#define DD 64
#define ONES 0x3F803F80u

// ---------------- device scratch (allocation-free) ----------------
__device__ float g_rowsum[NN];
__device__ float g_colsum[NN];
__device__ __align__(16) __nv_bfloat16 g_adjbf[67108864];  // adj bf16 row-major
__device__ __align__(16) __nv_bfloat16 g_Qt[128 * NN];     // Q^T [n][k]
__device__ __align__(16) __nv_bfloat16 g_Pt[128 * NN];     // P^T [n][k]
__device__ __align__(16) float g_RiP[2][NN * 128];         // adj   @ Q split-K partials
__device__ __align__(16) float g_RuP[2][NN * 128];         // adj^T @ P split-K partials

__device__ __forceinline__ uint32_t smem_u32(const void* p) {
    uint32_t a;
    asm("{ .reg .u64 t; cvta.to.shared.u64 t, %1; cvt.u32.u64 %0, t; }" : "=r"(a) : "l"(p));
    return a;
}
__device__ __forceinline__ void cpa16(uint32_t s, const void* g) {
    asm volatile("cp.async.cg.shared.global [%0], [%1], 16;" :: "r"(s), "l"(g) : "memory");
}
__device__ __forceinline__ uint32_t bf2pk(float lo, float hi) {
    __nv_bfloat162 b = __float22bfloat162_rn(make_float2(lo, hi));
    return *(uint32_t*)&b;
}
__device__ __forceinline__ void mma_bf16(float* c, uint32_t a0, uint32_t a1, uint32_t a2,
                                         uint32_t a3, uint32_t b0, uint32_t b1) {
    asm volatile(
        "mma.sync.aligned.m16n8k16.row.col.f32.bf16.bf16.f32 "
        "{%0,%1,%2,%3}, {%4,%5,%6,%7}, {%8,%9}, {%0,%1,%2,%3};"
        : "+f"(c[0]), "+f"(c[1]), "+f"(c[2]), "+f"(c[3])
        : "r"(a0), "r"(a1), "r"(a2), "r"(a3), "r"(b0), "r"(b1));
}

// ---------------- 1) streaming convert fp32 -> bf16 (+ zero row/col sums), MLP=4 ----------
__global__ void __launch_bounds__(256) convert_kernel(const float* __restrict__ adj) {
    int tid = threadIdx.x;
    int gid = blockIdx.x * 256 + tid;
    if (gid < NN) { g_colsum[gid] = 0.f; g_rowsum[gid] = 0.f; }  // replay-safe re-zero

    const int NF4 = NN * NN / 4;
    const float4* in = (const float4*)adj;
    uint2* outp = (uint2*)g_adjbf;
    for (int base = blockIdx.x * 1024 + tid; base < NF4; base += 4096 * 1024) {
        float4 v0 = in[base];
        float4 v1 = in[base + 256];
        float4 v2 = in[base + 512];
        float4 v3 = in[base + 768];
        uint2 o0, o1, o2, o3;
        o0.x = bf2pk(v0.x, v0.y); o0.y = bf2pk(v0.z, v0.w);
        o1.x = bf2pk(v1.x, v1.y); o1.y = bf2pk(v1.z, v1.w);
        o2.x = bf2pk(v2.x, v2.y); o2.y = bf2pk(v2.z, v2.w);
        o3.x = bf2pk(v3.x, v3.y); o3.y = bf2pk(v3.z, v3.w);
        outp[base] = o0;
        outp[base + 256] = o1;
        outp[base + 512] = o2;
        outp[base + 768] = o3;
    }
}

// ---------------- 2) tensor-core row/col sums: 256 CTAs (64-row slab x K-half) -----------
// blockIdx.x: bit0 = K-half, bits1.. = row slab. 32 tiles of [64 x 128] per CTA.
// Rowsum: warps 0-3 accumulate locally, end-of-kernel atomicAdd (2 CTAs per row).
// Colsum: per-tile atomics (arrays pre-zeroed by convert_kernel).
#define SROWS 64
#define SCOLS 128
__global__ void __launch_bounds__(256) sums_kernel() {
    __shared__ __align__(16) __nv_bfloat16 st[3][SROWS * SCOLS];
    int tid = threadIdx.x, lane = tid & 31, wid = tid >> 5;
    int r0 = (blockIdx.x >> 1) * SROWS;
    int khalf = (blockIdx.x & 1) * 4096;  // column offset (elements)

    int lr = tid >> 2, lc0 = (tid & 3) * 4;
    const char* gp = (const char*)(g_adjbf + (size_t)(r0 + lr) * NN + khalf) + lc0 * 16;
    uint32_t sbase = smem_u32(st);
    uint32_t sto[4];
#pragma unroll
    for (int j = 0; j < 4; j++)
        sto[j] = lr * 256 + (((lc0 + j) ^ (lr & 7)) << 4);

#pragma unroll
    for (int s = 0; s < 2; s++) {
#pragma unroll
        for (int j = 0; j < 4; j++)
            cpa16(sbase + s * (SROWS * SCOLS * 2) + sto[j], gp + (size_t)s * 256 + j * 16);
        asm volatile("cp.async.commit_group;" ::: "memory");
    }

    float rc[4] = {0.f, 0.f, 0.f, 0.f};

    for (int it = 0; it < 32; it++) {
        if (it < 30) asm volatile("cp.async.wait_group 1;" ::: "memory");
        else         asm volatile("cp.async.wait_group 0;" ::: "memory");
        __syncthreads();
        if (it + 2 < 32) {
            int s = (it + 2) % 3;
#pragma unroll
            for (int j = 0; j < 4; j++)
                cpa16(sbase + s * (SROWS * SCOLS * 2) + sto[j],
                      gp + (size_t)(it + 2) * 256 + j * 16);
            asm volatile("cp.async.commit_group;" ::: "memory");
        }
        uint32_t buf = sbase + (it % 3) * (SROWS * SCOLS * 2);

        if (wid < 4) {
            int aRow = wid * 16 + (lane & 15);
            int ax = aRow & 7;
#pragma unroll
            for (int kc = 0; kc < 8; kc++) {
                uint32_t a0, a1, a2, a3;
                uint32_t addr = buf + aRow * 256 + ((((kc << 1) | (lane >> 4)) ^ ax) << 4);
                asm volatile("ldmatrix.sync.aligned.m8n8.x4.shared.b16 {%0,%1,%2,%3}, [%4];"
                             : "=r"(a0), "=r"(a1), "=r"(a2), "=r"(a3) : "r"(addr));
                mma_bf16(rc, a0, a1, a2, a3, ONES, ONES);
            }
        }

        float cc0[4] = {0.f, 0.f, 0.f, 0.f}, cc1[4] = {0.f, 0.f, 0.f, 0.f};
        int srow0 = ((lane >> 4) & 1) * 8 + (lane & 7);
        int sc = wid * 2 + ((lane >> 3) & 1);
#pragma unroll
        for (int kc = 0; kc < 4; kc++) {
            int srow = kc * 16 + srow0;
            uint32_t b0, b1, b2, b3;
            uint32_t addr = buf + srow * 256 + ((sc ^ (srow & 7)) << 4);
            asm volatile("ldmatrix.sync.aligned.m8n8.x4.trans.shared.b16 {%0,%1,%2,%3}, [%4];"
                         : "=r"(b0), "=r"(b1), "=r"(b2), "=r"(b3) : "r"(addr));
            mma_bf16(cc0, ONES, ONES, ONES, ONES, b0, b2);
            mma_bf16(cc1, ONES, ONES, ONES, ONES, b1, b3);
        }
        if (lane < 4) {
            int colb = khalf + it * 128 + wid * 16 + 2 * lane;
            atomicAdd(&g_colsum[colb + 0], cc0[0]);
            atomicAdd(&g_colsum[colb + 1], cc0[1]);
            atomicAdd(&g_colsum[colb + 8], cc1[0]);
            atomicAdd(&g_colsum[colb + 9], cc1[1]);
        }
    }

    if (wid < 4 && (lane & 3) == 0) {
        int row = r0 + wid * 16 + (lane >> 2);
        atomicAdd(&g_rowsum[row], rc[0]);
        atomicAdd(&g_rowsum[row + 8], rc[2]);
    }
}

// ---------------- 3) build Qt/Pt (bf16, [n][k]); 16 k-rows per block ----------------
__global__ void __launch_bounds__(256) prep_kernel(const float* __restrict__ user,
                                                   const float* __restrict__ item,
                                                   const float* __restrict__ W1) {
    int var = blockIdx.y;  // 0 -> Pt (src=item, scale=rsqrt(rowsum)), 1 -> Qt
    const float* src = var ? user : item;
    const float* pas = var ? item : user;
    const float* sums = var ? g_colsum : g_rowsum;
    __nv_bfloat16* out = var ? g_Qt : g_Pt;

    __shared__ __align__(16) float Ws[DD * DD];
    __shared__ float Xs[16 * DD];
    __shared__ __nv_bfloat16 T[128 * 18];
    int tid = threadIdx.x;
    for (int i = tid; i < DD * DD; i += 256) Ws[i] = W1[i];
    int k0 = blockIdx.x * 16;
    for (int i = tid; i < 16 * DD; i += 256) Xs[i] = src[k0 * DD + i];
    __syncthreads();

    int row = tid >> 4;
    int g4 = (tid & 15) * 4;
    float a0 = 0.f, a1 = 0.f, a2 = 0.f, a3 = 0.f;
#pragma unroll 8
    for (int k = 0; k < DD; k++) {
        float x = Xs[row * DD + k];
        float4 w = *(const float4*)&Ws[k * DD + g4];
        a0 += x * w.x; a1 += x * w.y; a2 += x * w.z; a3 += x * w.w;
    }
    int gr = k0 + row;
    float s = rsqrtf(sums[gr]);
    T[(g4 + 0) * 18 + row] = __float2bfloat16(s * a0);
    T[(g4 + 1) * 18 + row] = __float2bfloat16(s * a1);
    T[(g4 + 2) * 18 + row] = __float2bfloat16(s * a2);
    T[(g4 + 3) * 18 + row] = __float2bfloat16(s * a3);
    const float* p = pas + gr * DD;
#pragma unroll
    for (int j = 0; j < 4; j++)
        T[(64 + g4 + j) * 18 + row] = __float2bfloat16(s * p[g4 + j]);
    __syncthreads();

    if (tid < 128) {
        int n = tid;
        __align__(16) __nv_bfloat16 v[16];
#pragma unroll
        for (int k = 0; k < 16; k++) v[k] = T[n * 18 + k];
        uint4* dst = (uint4*)(out + (size_t)n * NN + k0);
        dst[0] = ((uint4*)v)[0];
        dst[1] = ((uint4*)v)[1];
    }
}

// ---------------- 4) GEMMs: split-K=2, ping-pong pipeline, occupancy 2 (R14/R16 proven) --
#define NST 2
#define ASTG 16384
#define NITER2 64
#define SMEM_GEMM 67584   // >= max(2*NST*ASTG=64KB, transpose 128*132*4=67584)

__global__ void __launch_bounds__(256, 2) gemm_kernel() {
    extern __shared__ char sm[];
    uint32_t sA = smem_u32(sm);
    uint32_t sB = sA + NST * ASTG;

    int tid = threadIdx.x;
    int lane = tid & 31, wid = tid >> 5;
    int warpM = wid & 3, warpN = wid >> 2;  // 4x2 warps, warp tile 32m x 64n
    int z = blockIdx.z;
    size_t kbase = (size_t)z * 4096;

    float c[2][8][4];
#pragma unroll
    for (int f = 0; f < 2; f++)
#pragma unroll
        for (int n = 0; n < 8; n++)
#pragma unroll
            for (int j = 0; j < 4; j++) c[f][n][j] = 0.f;

    if (blockIdx.y == 0) {
        // ---------------- GEMM1: RiP[z] = adjbf @ Qt (K-half) ----------------
        int m0 = blockIdx.x * 128;
        float* Cg = g_RiP[z];
        int lr = tid >> 1, lc0 = (tid & 1) * 4;
        const char* gAp = (const char*)(g_adjbf + (size_t)(m0 + lr) * NN + kbase) + lc0 * 16;
        const char* gBp = (const char*)(g_Qt + (size_t)lr * NN + kbase) + lc0 * 16;
        uint32_t sto[4];
#pragma unroll
        for (int j = 0; j < 4; j++)
            sto[j] = lr * 128 + (((lc0 + j) ^ (lr & 7)) << 4);

        int aRow[2], aX[2];
#pragma unroll
        for (int f = 0; f < 2; f++) {
            aRow[f] = warpM * 32 + f * 16 + (lane & 15);
            aX[f] = aRow[f] & 7;
        }
        int ah = lane >> 4;
        int bRow[4], bX[4];
#pragma unroll
        for (int g = 0; g < 4; g++) {
            bRow[g] = warpN * 64 + g * 16 + (lane >> 4) * 8 + (lane & 7);
            bX[g] = bRow[g] & 7;
        }
        int bh = (lane >> 3) & 1;

#pragma unroll
        for (int j = 0; j < 4; j++) {
            cpa16(sA + sto[j], gAp + j * 16);
            cpa16(sB + sto[j], gBp + j * 16);
        }
        asm volatile("cp.async.commit_group;" ::: "memory");

        for (int it = 0; it < NITER2; it++) {
            asm volatile("cp.async.wait_group 0;" ::: "memory");
            __syncthreads();
            if (it + 1 < NITER2) {
                int s = (it + 1) & 1;
                size_t kb = (size_t)(it + 1) * 128;
#pragma unroll
                for (int j = 0; j < 4; j++) {
                    cpa16(sA + s * ASTG + sto[j], gAp + kb + j * 16);
                    cpa16(sB + s * ASTG + sto[j], gBp + kb + j * 16);
                }
                asm volatile("cp.async.commit_group;" ::: "memory");
            }
            uint32_t ba = sA + (it & 1) * ASTG;
            uint32_t bb = sB + (it & 1) * ASTG;
#pragma unroll
            for (int ks = 0; ks < 4; ks++) {
                uint32_t am[2][4], bn[4][4];
#pragma unroll
                for (int f = 0; f < 2; f++) {
                    uint32_t addr = ba + aRow[f] * 128 + ((((ks << 1) | ah) ^ aX[f]) << 4);
                    asm volatile("ldmatrix.sync.aligned.m8n8.x4.shared.b16 {%0,%1,%2,%3}, [%4];"
                                 : "=r"(am[f][0]), "=r"(am[f][1]), "=r"(am[f][2]), "=r"(am[f][3])
                                 : "r"(addr));
                }
#pragma unroll
                for (int g = 0; g < 4; g++) {
                    uint32_t addr = bb + bRow[g] * 128 + ((((ks << 1) | bh) ^ bX[g]) << 4);
                    asm volatile("ldmatrix.sync.aligned.m8n8.x4.shared.b16 {%0,%1,%2,%3}, [%4];"
                                 : "=r"(bn[g][0]), "=r"(bn[g][1]), "=r"(bn[g][2]), "=r"(bn[g][3])
                                 : "r"(addr));
                }
#pragma unroll
                for (int f = 0; f < 2; f++)
#pragma unroll
                    for (int g = 0; g < 4; g++) {
                        mma_bf16(c[f][g * 2], am[f][0], am[f][1], am[f][2], am[f][3],
                                 bn[g][0], bn[g][1]);
                        mma_bf16(c[f][g * 2 + 1], am[f][0], am[f][1], am[f][2], am[f][3],
                                 bn[g][2], bn[g][3]);
                    }
            }
        }
#pragma unroll
        for (int f = 0; f < 2; f++) {
            int row = m0 + warpM * 32 + f * 16 + (lane >> 2);
#pragma unroll
            for (int n = 0; n < 8; n++) {
                int col = warpN * 64 + n * 8 + (lane & 3) * 2;
                *(float2*)&Cg[(size_t)row * 128 + col] = make_float2(c[f][n][0], c[f][n][1]);
                *(float2*)&Cg[(size_t)(row + 8) * 128 + col] = make_float2(c[f][n][2], c[f][n][3]);
            }
        }
    } else {
        // ---------------- GEMM2: RuT partial = Pt @ adjbf[Khalf, n-tile] ----------------
        int n0 = blockIdx.x * 128;
        float* Cg = g_RuP[z];
        int lrA = tid >> 1, lcA = (tid & 1) * 4;
        const char* gAp = (const char*)(g_Pt + (size_t)lrA * NN + kbase) + lcA * 16;
        uint32_t stoA[4];
#pragma unroll
        for (int j = 0; j < 4; j++)
            stoA[j] = lrA * 128 + (((lcA + j) ^ (lrA & 7)) << 4);

        int lrB = tid >> 2, lcB = (tid & 3) * 4;
        const char* gBp = (const char*)(g_adjbf + (size_t)(kbase + lrB) * NN + n0) + lcB * 16;
        uint32_t stoB[4];
#pragma unroll
        for (int j = 0; j < 4; j++)
            stoB[j] = lrB * 256 + (((lcB + j) ^ (lrB & 7)) << 4);

        int aRow[2], aX[2];
#pragma unroll
        for (int f = 0; f < 2; f++) {
            aRow[f] = warpM * 32 + f * 16 + (lane & 15);
            aX[f] = aRow[f] & 7;
        }
        int ah = lane >> 4;
        int srow0 = ((lane >> 4) & 1) * 8 + (lane & 7);
        int scb = (lane >> 3) & 1;

#pragma unroll
        for (int j = 0; j < 4; j++) {
            cpa16(sA + stoA[j], gAp + j * 16);
            cpa16(sB + stoB[j], gBp + j * 16);
        }
        asm volatile("cp.async.commit_group;" ::: "memory");

        for (int it = 0; it < NITER2; it++) {
            asm volatile("cp.async.wait_group 0;" ::: "memory");
            __syncthreads();
            if (it + 1 < NITER2) {
                int s = (it + 1) & 1;
                size_t kit = (size_t)(it + 1);
#pragma unroll
                for (int j = 0; j < 4; j++) {
                    cpa16(sA + s * ASTG + stoA[j], gAp + kit * 128 + j * 16);
                    cpa16(sB + s * ASTG + stoB[j], gBp + kit * 64 * NN * 2 + j * 16);
                }
                asm volatile("cp.async.commit_group;" ::: "memory");
            }
            uint32_t ba = sA + (it & 1) * ASTG;
            uint32_t bb = sB + (it & 1) * ASTG;
#pragma unroll
            for (int ks = 0; ks < 4; ks++) {
                uint32_t am[2][4], bn[4][4];
#pragma unroll
                for (int f = 0; f < 2; f++) {
                    uint32_t addr = ba + aRow[f] * 128 + ((((ks << 1) | ah) ^ aX[f]) << 4);
                    asm volatile("ldmatrix.sync.aligned.m8n8.x4.shared.b16 {%0,%1,%2,%3}, [%4];"
                                 : "=r"(am[f][0]), "=r"(am[f][1]), "=r"(am[f][2]), "=r"(am[f][3])
                                 : "r"(addr));
                }
                int srow = ks * 16 + srow0;
                int sxr = srow & 7;
#pragma unroll
                for (int g = 0; g < 4; g++) {
                    int sc = warpN * 8 + g * 2 + scb;
                    uint32_t addr = bb + srow * 256 + ((sc ^ sxr) << 4);
                    asm volatile("ldmatrix.sync.aligned.m8n8.x4.trans.shared.b16 {%0,%1,%2,%3}, [%4];"
                                 : "=r"(bn[g][0]), "=r"(bn[g][1]), "=r"(bn[g][2]), "=r"(bn[g][3])
                                 : "r"(addr));
                }
#pragma unroll
                for (int f = 0; f < 2; f++)
#pragma unroll
                    for (int g = 0; g < 4; g++) {
                        mma_bf16(c[f][g * 2], am[f][0], am[f][1], am[f][2], am[f][3],
                                 bn[g][0], bn[g][2]);
                        mma_bf16(c[f][g * 2 + 1], am[f][0], am[f][1], am[f][2], am[f][3],
                                 bn[g][1], bn[g][3]);
                    }
            }
        }

        // transpose epilogue
        __syncthreads();
        float* tr = (float*)sm;
#pragma unroll
        for (int f = 0; f < 2; f++) {
            int m = warpM * 32 + f * 16 + (lane >> 2);
#pragma unroll
            for (int n = 0; n < 8; n++) {
                int nc = warpN * 64 + n * 8 + (lane & 3) * 2;
                tr[nc * 132 + m] = c[f][n][0];
                tr[(nc + 1) * 132 + m] = c[f][n][1];
                tr[nc * 132 + m + 8] = c[f][n][2];
                tr[(nc + 1) * 132 + m + 8] = c[f][n][3];
            }
        }
        __syncthreads();
        for (int i = tid; i < 128 * 32; i += 256) {
            int r = i >> 5, q = i & 31;
            float4 v = *(float4*)&tr[r * 132 + q * 4];
            *(float4*)&Cg[(size_t)(n0 + r) * 128 + q * 4] = v;
        }
    }
}

// ---------------- 5) epilogue (sums split-K partials, inline rsqrt) ----------------
__global__ void __launch_bounds__(256) final_kernel(const float* __restrict__ user,
                                                    const float* __restrict__ item,
                                                    const float* __restrict__ W2,
                                                    float* __restrict__ out) {
    int var = blockIdx.y;
    const float* R0 = var ? g_RiP[0] : g_RuP[0];
    const float* R1 = var ? g_RiP[1] : g_RuP[1];
    const float* sums = var ? g_rowsum : g_colsum;
    const float* src = var ? user : item;
    const float* tgt = var ? item : user;
    float* o = out + (size_t)var * NN * DD;

    __shared__ __align__(16) float Ws[DD * DD];
    __shared__ float Hs[16 * DD];
    int tid = threadIdx.x;
    for (int i = tid; i < DD * DD; i += 256) Ws[i] = W2[i];

    int r0 = blockIdx.x * 16;
    int row = tid >> 4;
    int cg = (tid & 15) * 4;
    int gr = r0 + row;
    float s = rsqrtf(sums[gr]);
#pragma unroll
    for (int j = 0; j < 4; j++) {
        float rv = R0[gr * 128 + 64 + cg + j] + R1[gr * 128 + 64 + cg + j];
        Hs[row * DD + cg + j] = src[gr * DD + cg + j] * (s * rv);
    }
    __syncthreads();

    float acc[4] = {0.f, 0.f, 0.f, 0.f};
#pragma unroll 8
    for (int k = 0; k < DD; k++) {
        float hh = Hs[row * DD + k];
        float4 w = *(const float4*)&Ws[k * DD + cg];
        acc[0] += hh * w.x; acc[1] += hh * w.y; acc[2] += hh * w.z; acc[3] += hh * w.w;
    }
#pragma unroll
    for (int j = 0; j < 4; j++) {
        float rv = R0[gr * 128 + cg + j] + R1[gr * 128 + cg + j];
        float x = s * rv + acc[j] + tgt[gr * DD + cg + j];
        o[gr * DD + cg + j] = x > 0.f ? x : 0.2f * x;
    }
}

// ---------------- launch ----------------
extern "C" void kernel_launch(void* const* d_in, const int* in_sizes, int n_in,
                              void* d_out, int out_size) {
    const float* user = (const float*)d_in[0];
    const float* item = (const float*)d_in[1];
    const float* adj  = (const float*)d_in[2];
    const float* W1   = (const float*)d_in[3];
    const float* W2   = (const float*)d_in[4];
    float* out = (float*)d_out;

    cudaFuncSetAttribute(gemm_kernel, cudaFuncAttributeMaxDynamicSharedMemorySize, SMEM_GEMM);

    convert_kernel<<<4096, 256>>>(adj);
    sums_kernel<<<256, 256>>>();
    prep_kernel<<<dim3(512, 2), 256>>>(user, item, W1);
    gemm_kernel<<<dim3(64, 2, 2), 256, SMEM_GEMM>>>();
    final_kernel<<<dim3(512, 2), 256>>>(user, item, W2, out);
}